// round 3
// baseline (speedup 1.0000x reference)
#include <cuda_runtime.h>

// Problem constants
#define BB    16
#define TT    1000
#define FTOT  481
#define NF    96
#define NN    5          // FRAME_SIZE
#define NCOEF 30         // N*N + N
#define TF    (TT * NF)  // 96000

struct cplx { float re, im; };

__device__ __forceinline__ cplx cmul(cplx a, cplx b) {
    return { a.re * b.re - a.im * b.im, a.re * b.im + a.im * b.re };
}
__device__ __forceinline__ cplx csub(cplx a, cplx b) {
    return { a.re - b.re, a.im - b.im };
}
__device__ __forceinline__ cplx cdiv(cplx a, cplx b) {
    float inv = __frcp_rn(b.re * b.re + b.im * b.im);
    return { (a.re * b.re + a.im * b.im) * inv,
             (a.im * b.re - a.re * b.im) * inv };
}
__device__ __forceinline__ float cabs2(cplx a) { return a.re * a.re + a.im * a.im; }

// Fused kernel: one thread per output float2 element (b, t, f), f in [0, 481).
//   f <  96 : solve 5x5 complex system from coefs, apply FIR over 5 time taps.
//   f >= 96 : pass-through copy of spec.
__global__ __launch_bounds__(128)
void mfwf_fused_kernel(const float2* __restrict__ spec,
                       const float2* __restrict__ coefs,
                       float2* __restrict__ out) {
    int g = blockIdx.x * blockDim.x + threadIdx.x;
    if (g >= BB * TT * FTOT) return;

    int bt = g / FTOT;          // b * TT + t
    int f  = g - bt * FTOT;

    if (f >= NF) {
        // ---- pass-through ----
        out[g] = spec[g];
        return;
    }

    int b = bt / TT;
    int t = bt - b * TT;
    int tf = t * NF + f;

    // ---- Load augmented system [A | r] (tf contiguous per (b,k) slab) ----
    cplx A[NN][NN];
    cplx r[NN];
    int base = b * NCOEF * TF + tf;
#pragma unroll
    for (int n = 0; n < NN; n++) {
#pragma unroll
        for (int m = 0; m < NN; m++) {
            float2 v = __ldg(&coefs[base + (n * NN + m) * TF]);
            A[n][m] = { v.x, v.y };
        }
    }
#pragma unroll
    for (int n = 0; n < NN; n++) {
        float2 v = __ldg(&coefs[base + (NN * NN + n) * TF]);
        r[n] = { v.x, v.y };
    }

    // ---- Gaussian elimination with partial pivoting ----
#pragma unroll
    for (int k = 0; k < NN; k++) {
        // bubble max-magnitude pivot into row k (static indices => registers)
#pragma unroll
        for (int i = k + 1; i < NN; i++) {
            bool sw = cabs2(A[i][k]) > cabs2(A[k][k]);
            if (sw) {
#pragma unroll
                for (int j = 0; j < NN; j++) {
                    cplx tmp = A[k][j]; A[k][j] = A[i][j]; A[i][j] = tmp;
                }
                cplx tmp = r[k]; r[k] = r[i]; r[i] = tmp;
            }
        }
        // multiply by conj(pivot)/|pivot|^2 instead of complex divide
        float pinv = __frcp_rn(cabs2(A[k][k]));
        cplx prec = { A[k][k].re * pinv, -A[k][k].im * pinv };
#pragma unroll
        for (int i = k + 1; i < NN; i++) {
            cplx fac = cmul(A[i][k], prec);
#pragma unroll
            for (int j = k + 1; j < NN; j++)
                A[i][j] = csub(A[i][j], cmul(fac, A[k][j]));
            r[i] = csub(r[i], cmul(fac, r[k]));
        }
    }

    // ---- Back substitution ----
    cplx w[NN];
#pragma unroll
    for (int k = NN - 1; k >= 0; k--) {
        cplx s = r[k];
#pragma unroll
        for (int j = NN - 1; j > k; j--)
            s = csub(s, cmul(A[k][j], w[j]));
        w[k] = cdiv(s, A[k][k]);
    }

    // ---- y = sum_n x[t - 4 + n, f] * w[n] ----
    cplx y = { 0.f, 0.f };
#pragma unroll
    for (int n = 0; n < NN; n++) {
        int tt = t - (NN - 1) + n;
        if (tt >= 0) {
            float2 v = __ldg(&spec[(b * TT + tt) * FTOT + f]);
            cplx x = { v.x, v.y };
            y.re = fmaf(x.re, w[n].re, fmaf(-x.im, w[n].im, y.re));
            y.im = fmaf(x.re, w[n].im, fmaf( x.im, w[n].re, y.im));
        }
    }

    out[g] = make_float2(y.re, y.im);
}

extern "C" void kernel_launch(void* const* d_in, const int* in_sizes, int n_in,
                              void* d_out, int out_size) {
    const float2* spec  = (const float2*)d_in[0];
    const float2* coefs = (const float2*)d_in[1];
    float2* out = (float2*)d_out;

    int total = BB * TT * FTOT;   // 7,696,000 float2 outputs
    int threads = 128;
    int blocks = (total + threads - 1) / threads;
    mfwf_fused_kernel<<<blocks, threads>>>(spec, coefs, out);
}